// round 6
// baseline (speedup 1.0000x reference)
#include <cuda_runtime.h>
#include <math.h>

// Problem constants
#define NROWS 65536
#define NCENT 512
#define DIM   128

#define BM 128           // rows per block
#define BN 128           // centroids per c-tile
#define NTHREADS 256
#define TM 8
#define TN 8

// padded smem strides
#define ZS_STRIDE  129   // z_s[k][r], odd stride -> conflict-free transpose store
#define MUS_STRIDE 132   // mu_s[k][c], 16B-aligned rows for float4 loads

#define ZS_FLOATS   (DIM * ZS_STRIDE)               // 16512
#define MUS_FLOATS  (DIM * MUS_STRIDE)              // 16896
#define SMEM_FLOATS (ZS_FLOATS + MUS_FLOATS + BM)   // + z2_s[128]
#define SMEM_BYTES  (SMEM_FLOATS * 4)

// scratch (no cudaMalloc allowed)
__device__ float g_m2[NCENT];
__device__ float g_partials[NROWS / BM];   // 512 block partial sums

// ---------------------------------------------------------------------------
// Kernel 0: m2[c] = sum_d mu[c][d]^2
// ---------------------------------------------------------------------------
__global__ void m2_kernel(const float* __restrict__ mu) {
    int c = threadIdx.x;                  // 512 threads, 1 block
    const float4* p = reinterpret_cast<const float4*>(mu + (size_t)c * DIM);
    float s = 0.f;
#pragma unroll
    for (int i = 0; i < DIM / 4; i++) {
        float4 v = p[i];
        s += v.x * v.x + v.y * v.y + v.z * v.z + v.w * v.w;
    }
    g_m2[c] = s;
}

// ---------------------------------------------------------------------------
// Kernel 1: fused GEMM + min-distance. Each block: 128 rows x all 512 centroids.
// ---------------------------------------------------------------------------
__global__ void __launch_bounds__(NTHREADS, 1)
kmeans_main_kernel(const float* __restrict__ z, const float* __restrict__ mu) {
    extern __shared__ float sm[];
    float* z_s  = sm;                         // [DIM][ZS_STRIDE]  (k-major, transposed)
    float* mu_s = sm + ZS_FLOATS;             // [DIM][MUS_STRIDE] (k-major, transposed)
    float* z2_s = mu_s + MUS_FLOATS;          // [BM]
    float* red  = sm;                         // aliases z_s after compute (128*17 floats)

    const int tid  = threadIdx.x;
    const int row0 = blockIdx.x * BM;

    // ---- load z tile, transposed: z_s[d][r] = z[row0+r][d] -------------
    // lanes vary d fastest -> coalesced gmem; smem bank = (d + r) % 32 -> conflict-free
    for (int i = tid; i < BM * DIM; i += NTHREADS) {
        int r = i >> 7;          // / DIM
        int d = i & (DIM - 1);
        z_s[d * ZS_STRIDE + r] = z[(size_t)(row0 + r) * DIM + d];
    }
    __syncthreads();

    // ---- z2 per row ------------------------------------------------------
    if (tid < BM) {
        float s = 0.f;
#pragma unroll 8
        for (int k = 0; k < DIM; k++) {
            float v = z_s[k * ZS_STRIDE + tid];
            s += v * v;
        }
        z2_s[tid] = s;
    }

    // thread -> (txIdx, tyIdx) in 16x16 grid; warp covers 8 cols x 4 row-groups
    const int w = tid >> 5, l = tid & 31;
    const int txIdx = ((w & 1) << 3) | (l & 7);     // 0..15
    const int tyIdx = ((w >> 1) << 2) | (l >> 3);   // 0..15
    const int txB = txIdx * TN;
    const int tyB = tyIdx * TM;

    float rowmin[TM];
#pragma unroll
    for (int j = 0; j < TM; j++) rowmin[j] = 3.402823466e38f;

    for (int ct = 0; ct < NCENT / BN; ++ct) {
        // ---- load mu tile, transposed: mu_s[d][cc] = mu[ct*BN+cc][d] ----
        for (int i = tid; i < BN * DIM / 4; i += NTHREADS) {
            int cc = i >> 5;         // / 32
            int d4 = i & 31;
            float4 v = *reinterpret_cast<const float4*>(
                mu + (size_t)(ct * BN + cc) * DIM + d4 * 4);
            mu_s[(d4 * 4 + 0) * MUS_STRIDE + cc] = v.x;
            mu_s[(d4 * 4 + 1) * MUS_STRIDE + cc] = v.y;
            mu_s[(d4 * 4 + 2) * MUS_STRIDE + cc] = v.z;
            mu_s[(d4 * 4 + 3) * MUS_STRIDE + cc] = v.w;
        }
        __syncthreads();

        float acc[TM][TN];
#pragma unroll
        for (int j = 0; j < TM; j++)
#pragma unroll
            for (int jj = 0; jj < TN; jj++) acc[j][jj] = 0.f;

#pragma unroll 4
        for (int k = 0; k < DIM; k++) {
            float a[TM], b[TN];
            float4 b0 = *reinterpret_cast<const float4*>(mu_s + k * MUS_STRIDE + txB);
            float4 b1 = *reinterpret_cast<const float4*>(mu_s + k * MUS_STRIDE + txB + 4);
            b[0] = b0.x; b[1] = b0.y; b[2] = b0.z; b[3] = b0.w;
            b[4] = b1.x; b[5] = b1.y; b[6] = b1.z; b[7] = b1.w;
#pragma unroll
            for (int j = 0; j < TM; j++) a[j] = z_s[k * ZS_STRIDE + tyB + j];
#pragma unroll
            for (int j = 0; j < TM; j++)
#pragma unroll
                for (int jj = 0; jj < TN; jj++)
                    acc[j][jj] += a[j] * b[jj];
        }

        // ---- epilogue: d2 = z2 + m2 - 2*dot, keep running min ----------
#pragma unroll
        for (int jj = 0; jj < TN; jj++) {
            float m2v = g_m2[ct * BN + txB + jj];
#pragma unroll
            for (int j = 0; j < TM; j++) {
                float d2 = z2_s[tyB + j] + m2v - 2.f * acc[j][jj];
                rowmin[j] = fminf(rowmin[j], d2);
            }
        }
        __syncthreads();   // before next mu tile overwrites mu_s
    }

    // ---- cross-thread min (16 tx lanes per row), then sqrt+sum ----------
#pragma unroll
    for (int j = 0; j < TM; j++) red[(tyB + j) * 17 + txIdx] = rowmin[j];
    __syncthreads();

    float dist = 0.f;
    if (tid < BM) {
        float m = red[tid * 17];
#pragma unroll
        for (int i = 1; i < 16; i++) m = fminf(m, red[tid * 17 + i]);
        dist = sqrtf(fmaxf(m, 0.f));
    }
    // block sum (threads >=128 contribute 0)
#pragma unroll
    for (int o = 16; o; o >>= 1) dist += __shfl_down_sync(0xffffffffu, dist, o);
    __shared__ float sh[8];
    if (l == 0) sh[w] = dist;
    __syncthreads();
    if (tid == 0) {
        float s = 0.f;
#pragma unroll
        for (int i = 0; i < 8; i++) s += sh[i];
        g_partials[blockIdx.x] = s;
    }
}

// ---------------------------------------------------------------------------
// Kernel 2: deterministic final reduction of 512 partials -> mean
// ---------------------------------------------------------------------------
__global__ void reduce_kernel(float* __restrict__ out) {
    __shared__ float sh[16];
    int tid = threadIdx.x;                 // 512 threads
    float v = g_partials[tid];
#pragma unroll
    for (int o = 16; o; o >>= 1) v += __shfl_down_sync(0xffffffffu, v, o);
    if ((tid & 31) == 0) sh[tid >> 5] = v;
    __syncthreads();
    if (tid < 16) {
        float x = sh[tid];
#pragma unroll
        for (int o = 8; o; o >>= 1) x += __shfl_down_sync(0xffffu, x, o);
        if (tid == 0) out[0] = x / (float)NROWS;
    }
}

// ---------------------------------------------------------------------------
extern "C" void kernel_launch(void* const* d_in, const int* in_sizes, int n_in,
                              void* d_out, int out_size) {
    const float* z  = (const float*)d_in[0];   // (65536,1,128) contiguous
    const float* mu = (const float*)d_in[1];   // (512,128)
    float* out = (float*)d_out;

    cudaFuncSetAttribute(kmeans_main_kernel,
                         cudaFuncAttributeMaxDynamicSharedMemorySize, SMEM_BYTES);

    m2_kernel<<<1, NCENT>>>(mu);
    kmeans_main_kernel<<<NROWS / BM, NTHREADS, SMEM_BYTES>>>(z, mu);
    reduce_kernel<<<1, NCENT>>>(out);
}

// round 8
// speedup vs baseline: 3.9012x; 3.9012x over previous
#include <cuda_runtime.h>
#include <stdint.h>
#include <math.h>

// ---------------- problem constants ----------------
#define NROWS 65536
#define NCENT 512
#define DIM   128
#define BM    128
#define BN    128
#define NTILES (NCENT / BN)      // 4
#define NTHREADS 256

// ---------------- smem layout (bytes) ----------------
// A fragments: 8 mtiles x 16 ksteps x 33 (32 lanes + 1 pad slot) x 4 floats
#define A_FLOATS (8 * 16 * 33 * 4)          // 16896
#define A_BYTES  (A_FLOATS * 4)             // 67584
#define B_BYTES  65536                      // 16 nt x 16 ks x 32 lanes x 2 floats
#define B_OFF(b) (A_BYTES + (b) * B_BYTES)
#define M2_OFF   (A_BYTES + 2 * B_BYTES)    // 198656
#define Z2_OFF   (M2_OFF + NCENT * 4)       // 200704
#define RED_OFF  (Z2_OFF + BM * 4)          // 201216
#define SMEM_BYTES (RED_OFF + BM * 4 * 4 + 64)

// ---------------- device scratch (no cudaMalloc allowed) ----------------
__device__ float g_m2[NCENT];
__device__ float g_partials[NROWS / BM];
// mu pre-converted to tf32 in B-fragment layout: [ct][nt*16+ks][lane][2]
__device__ uint4 g_mub[NTILES][B_BYTES / 16];

// ================= PTX helpers =================
__device__ __forceinline__ uint32_t smem_u32(const void* p) {
    uint32_t a;
    asm("{ .reg .u64 t; cvta.to.shared.u64 t, %1; cvt.u32.u64 %0, t; }"
        : "=r"(a) : "l"(p));
    return a;
}
__device__ __forceinline__ uint32_t f2tf32(float f) {
    uint32_t r;
    asm("cvt.rna.tf32.f32 %0, %1;" : "=r"(r) : "f"(f));
    return r;
}
__device__ __forceinline__ void cp_async16(uint32_t s, const void* g) {
    asm volatile("cp.async.cg.shared.global [%0], [%1], 16;" :: "r"(s), "l"(g));
}
#define CP_COMMIT()  asm volatile("cp.async.commit_group;" ::: "memory")
#define CP_WAIT(n)   asm volatile("cp.async.wait_group %0;" :: "n"(n) : "memory")

// D[16x8] += A[16x8] * B[8x8], tf32 inputs, f32 accumulate
__device__ __forceinline__ void mma_tf32(float* d, const uint32_t* a, const uint32_t* b) {
    asm volatile(
        "mma.sync.aligned.m16n8k8.row.col.f32.tf32.tf32.f32 "
        "{%0,%1,%2,%3}, {%4,%5,%6,%7}, {%8,%9}, {%0,%1,%2,%3};"
        : "+f"(d[0]), "+f"(d[1]), "+f"(d[2]), "+f"(d[3])
        : "r"(a[0]), "r"(a[1]), "r"(a[2]), "r"(a[3]), "r"(b[0]), "r"(b[1]));
}
__device__ __forceinline__ float warp_sum(float p) {
#pragma unroll
    for (int o = 16; o; o >>= 1) p += __shfl_xor_sync(0xffffffffu, p, o);
    return p;
}

// ================= kernel 0: mu -> tf32 B-fragments + m2 =================
// B fragment (m16n8k8.row.col): lane = g*4+tig holds b0=(k=tig,n=g), b1=(k=tig+4,n=g)
__global__ void mu_prep_kernel(const float* __restrict__ mu) {
    const int ct = blockIdx.x, tid = threadIdx.x, w = tid >> 5, lane = tid & 31;
    float* dst = reinterpret_cast<float*>(g_mub[ct]);
    const float4* mp = reinterpret_cast<const float4*>(mu);
#pragma unroll
    for (int it = 0; it < 16; ++it) {
        int nl = w + it * 8;                       // local centroid 0..127
        float4 v = mp[(size_t)(ct * BN + nl) * 32 + lane];
        float p = warp_sum(v.x * v.x + v.y * v.y + v.z * v.z + v.w * v.w);
        if (lane == 0) g_m2[ct * BN + nl] = p;
        int nt = nl >> 3, gg = nl & 7;
        float e[4] = { v.x, v.y, v.z, v.w };
#pragma unroll
        for (int j = 0; j < 4; ++j) {
            int c = lane * 4 + j;
            int ks = c >> 3, cc = c & 7, tg = cc & 3, rg = cc >> 2;
            dst[(((nt * 16 + ks) * 32) + gg * 4 + tg) * 2 + rg] =
                __uint_as_float(f2tf32(e[j]));
        }
    }
}

// ================= main kernel: tf32 mma.sync GEMM + min epilogue =========
__global__ void __launch_bounds__(NTHREADS, 1)
kmeans_mma_kernel(const float* __restrict__ z) {
    extern __shared__ float sm[];
    float* A_s  = sm;
    float* m2_s = sm + M2_OFF / 4;
    float* z2_s = sm + Z2_OFF / 4;
    float* red  = sm + RED_OFF / 4;
    const uint32_t sb = smem_u32(sm);

    const int tid = threadIdx.x, w = tid >> 5, lane = tid & 31;
    const int warp_m = w >> 2, warp_n = w & 3;
    const int g = lane >> 2, tig = lane & 3;
    const int row0 = blockIdx.x * BM;
    const float4* zp = reinterpret_cast<const float4*>(z);

    // ---- A staging: z -> tf32 fragments (padded stride 33) + exact z2 ----
    // A fragment: lane g*4+tig holds a0=(g,tig) a1=(g+8,tig) a2=(g,tig+4) a3=(g+8,tig+4)
#pragma unroll
    for (int it = 0; it < 16; ++it) {
        int r = w + it * 8;
        float4 v = zp[(size_t)(row0 + r) * 32 + lane];
        float p = warp_sum(v.x * v.x + v.y * v.y + v.z * v.z + v.w * v.w);
        if (lane == 0) z2_s[r] = p;
        int mt = r >> 4, gg = r & 7, half = (r >> 3) & 1;
        float e[4] = { v.x, v.y, v.z, v.w };
#pragma unroll
        for (int j = 0; j < 4; ++j) {
            int c = lane * 4 + j;
            int ks = c >> 3, cc = c & 7, tg = cc & 3, hi = cc >> 2;
            A_s[((mt * 16 + ks) * 33 + gg * 4 + tg) * 4 + half + 2 * hi] =
                __uint_as_float(f2tf32(e[j]));
        }
    }
    for (int i = tid; i < NCENT; i += NTHREADS) m2_s[i] = g_m2[i];

    // ---- prefetch B tile 0 ----
    {
        const uint4* src = g_mub[0];
        for (int i = tid; i < B_BYTES / 16; i += NTHREADS)
            cp_async16(sb + B_OFF(0) + i * 16, src + i);
        CP_COMMIT();
    }

    float rowmin[8];
#pragma unroll
    for (int k = 0; k < 8; ++k) rowmin[k] = 3.402823466e38f;

    // ---- mainloop over 4 N-tiles, double-buffered B via cp.async ----
    for (int ct = 0; ct < NTILES; ++ct) {
        if (ct + 1 < NTILES) {
            const uint4* src = g_mub[ct + 1];
            uint32_t dst = sb + B_OFF((ct + 1) & 1);
            for (int i = tid; i < B_BYTES / 16; i += NTHREADS)
                cp_async16(dst + i * 16, src + i);
            CP_COMMIT();
            CP_WAIT(1);           // tile ct complete
        } else {
            CP_WAIT(0);
        }
        __syncthreads();          // covers A staging (ct=0) + B visibility

        float acc[4][4][4];
#pragma unroll
        for (int mt = 0; mt < 4; ++mt)
#pragma unroll
            for (int nt = 0; nt < 4; ++nt)
#pragma unroll
                for (int q = 0; q < 4; ++q) acc[mt][nt][q] = 0.f;

        const float* Bbuf = sm + B_OFF(ct & 1) / 4;
#pragma unroll 4
        for (int ks = 0; ks < 16; ++ks) {
            uint32_t a[4][4], b[4][2];
#pragma unroll
            for (int mt = 0; mt < 4; ++mt)
                *reinterpret_cast<uint4*>(a[mt]) = *reinterpret_cast<const uint4*>(
                    &A_s[(((warp_m * 4 + mt) * 16 + ks) * 33 + lane) * 4]);
#pragma unroll
            for (int nt = 0; nt < 4; ++nt)
                *reinterpret_cast<uint2*>(b[nt]) = *reinterpret_cast<const uint2*>(
                    &Bbuf[(((warp_n * 4 + nt) * 16 + ks) * 32 + lane) * 2]);
#pragma unroll
            for (int mt = 0; mt < 4; ++mt)
#pragma unroll
                for (int nt = 0; nt < 4; ++nt)
                    mma_tf32(acc[mt][nt], a[mt], b[nt]);
        }

        // ---- epilogue: d2 = z2 + m2 - 2*dot, running min ----
        // D frag: c0=(g,2tig) c1=(g,2tig+1) c2=(g+8,2tig) c3=(g+8,2tig+1)
#pragma unroll
        for (int mt = 0; mt < 4; ++mt) {
            int rb = warp_m * 64 + mt * 16 + g;
            float z2a = z2_s[rb], z2b = z2_s[rb + 8];
#pragma unroll
            for (int nt = 0; nt < 4; ++nt) {
                int cb = ct * BN + warp_n * 32 + nt * 8 + 2 * tig;
                float m0 = m2_s[cb], m1 = m2_s[cb + 1];
                rowmin[mt * 2]     = fminf(rowmin[mt * 2],
                                           fmaf(-2.f, acc[mt][nt][0], z2a + m0));
                rowmin[mt * 2]     = fminf(rowmin[mt * 2],
                                           fmaf(-2.f, acc[mt][nt][1], z2a + m1));
                rowmin[mt * 2 + 1] = fminf(rowmin[mt * 2 + 1],
                                           fmaf(-2.f, acc[mt][nt][2], z2b + m0));
                rowmin[mt * 2 + 1] = fminf(rowmin[mt * 2 + 1],
                                           fmaf(-2.f, acc[mt][nt][3], z2b + m1));
            }
        }
        __syncthreads();          // all reads of buf[ct&1] done before reuse
    }

    // ---- reduce min across the 4 tig lanes sharing each row ----
#pragma unroll
    for (int k = 0; k < 8; ++k) {
        float v = rowmin[k];
        v = fminf(v, __shfl_xor_sync(0xffffffffu, v, 1));
        v = fminf(v, __shfl_xor_sync(0xffffffffu, v, 2));
        rowmin[k] = v;
    }
    if (tig == 0) {
#pragma unroll
        for (int mt = 0; mt < 4; ++mt) {
            red[(warp_m * 64 + mt * 16 + g) * 4 + warp_n]     = rowmin[mt * 2];
            red[(warp_m * 64 + mt * 16 + 8 + g) * 4 + warp_n] = rowmin[mt * 2 + 1];
        }
    }
    __syncthreads();

    float dist = 0.f;
    if (tid < BM) {
        float m = fminf(fminf(red[tid * 4], red[tid * 4 + 1]),
                        fminf(red[tid * 4 + 2], red[tid * 4 + 3]));
        dist = sqrtf(fmaxf(m, 0.f));
    }
#pragma unroll
    for (int o = 16; o; o >>= 1) dist += __shfl_down_sync(0xffffffffu, dist, o);
    __shared__ float sh[8];
    if (lane == 0) sh[w] = dist;
    __syncthreads();
    if (tid == 0) {
        float s = 0.f;
#pragma unroll
        for (int i = 0; i < 8; i++) s += sh[i];
        g_partials[blockIdx.x] = s;
    }
}

// ================= kernel 2: deterministic final reduction ================
__global__ void reduce_kernel(float* __restrict__ out) {
    __shared__ float sh[16];
    int tid = threadIdx.x;                 // 512 threads
    float v = g_partials[tid];
#pragma unroll
    for (int o = 16; o; o >>= 1) v += __shfl_down_sync(0xffffffffu, v, o);
    if ((tid & 31) == 0) sh[tid >> 5] = v;
    __syncthreads();
    if (tid < 16) {
        float x = sh[tid];
#pragma unroll
        for (int o = 8; o; o >>= 1) x += __shfl_down_sync(0xffffu, x, o);
        if (tid == 0) out[0] = x / (float)NROWS;
    }
}

// ---------------------------------------------------------------------------
extern "C" void kernel_launch(void* const* d_in, const int* in_sizes, int n_in,
                              void* d_out, int out_size) {
    const float* z  = (const float*)d_in[0];   // (65536,1,128) contiguous
    const float* mu = (const float*)d_in[1];   // (512,128)
    float* out = (float*)d_out;

    cudaFuncSetAttribute(kmeans_mma_kernel,
                         cudaFuncAttributeMaxDynamicSharedMemorySize, SMEM_BYTES);

    mu_prep_kernel<<<NTILES, NTHREADS>>>(mu);
    kmeans_mma_kernel<<<NROWS / BM, NTHREADS, SMEM_BYTES>>>(z);
    reduce_kernel<<<1, NCENT>>>(out);
}

// round 12
// speedup vs baseline: 6.4166x; 1.6448x over previous
#include <cuda_runtime.h>
#include <cuda_fp16.h>
#include <stdint.h>
#include <math.h>

// ---------------- problem constants ----------------
#define NROWS 65536
#define NCENT 512
#define DIM   128
#define BM    128
#define BN    128
#define NTILES (NCENT / BN)      // 4
#define NTHREADS 256
#define NBLK   (NROWS / BM)      // 512

// ---------------- smem layout (uint32 word offsets) ----------------
// A fragments (fp16 pairs): 8 mt x 8 ks x 33(32 lanes + pad) x 4 words
#define A_WORDS   (8 * 8 * 33 * 4)            // 8448
#define BT_WORDS  (16 * 8 * 32 * 2)           // 8192 words = 32KB per B tile
#define B_W(b)    (A_WORDS + (b) * BT_WORDS)
#define M2_W      (A_WORDS + 2 * BT_WORDS)    // 24832
#define Z2_W      (M2_W + NCENT)              // 25344
#define SH_W      (Z2_W + BM)                 // 25472
#define SMEM_BYTES ((SH_W + 16) * 4)          // ~102KB -> 2 CTAs/SM

// ---------------- device scratch (no cudaMalloc allowed) ----------------
__device__ float g_m2[NCENT];
__device__ float g_partials[NBLK];
__device__ unsigned g_done = 0;   // atomicInc-wrap counter, self-resets each launch
// mu pre-converted to fp16 B-fragment images: [ct][(nt*8+ks)*32+lane]*2+rg words
__device__ uint4 g_mub[NTILES][BT_WORDS / 4];

// ================= PTX helpers =================
__device__ __forceinline__ uint32_t smem_u32(const void* p) {
    uint32_t a;
    asm("{ .reg .u64 t; cvta.to.shared.u64 t, %1; cvt.u32.u64 %0, t; }"
        : "=r"(a) : "l"(p));
    return a;
}
__device__ __forceinline__ void cp_async16(uint32_t s, const void* g) {
    asm volatile("cp.async.cg.shared.global [%0], [%1], 16;" :: "r"(s), "l"(g));
}
#define CP_COMMIT()  asm volatile("cp.async.commit_group;" ::: "memory")
#define CP_WAIT(n)   asm volatile("cp.async.wait_group %0;" :: "n"(n) : "memory")

// D[16x8](f32) += A[16x16](f16) * B[16x8](f16)
__device__ __forceinline__ void mma_fp16(float* d, const uint32_t* a, const uint32_t* b) {
    asm volatile(
        "mma.sync.aligned.m16n8k16.row.col.f32.f16.f16.f32 "
        "{%0,%1,%2,%3}, {%4,%5,%6,%7}, {%8,%9}, {%0,%1,%2,%3};"
        : "+f"(d[0]), "+f"(d[1]), "+f"(d[2]), "+f"(d[3])
        : "r"(a[0]), "r"(a[1]), "r"(a[2]), "r"(a[3]), "r"(b[0]), "r"(b[1]));
}
__device__ __forceinline__ float warp_sum(float p) {
#pragma unroll
    for (int o = 16; o; o >>= 1) p += __shfl_xor_sync(0xffffffffu, p, o);
    return p;
}
__device__ __forceinline__ uint32_t h2bits(float a, float b) {
    __half2 h = __floats2half2_rn(a, b);
    return *reinterpret_cast<uint32_t*>(&h);
}

// ================= kernel 0: mu -> fp16 B-fragments + m2 =================
// B frag (m16n8k16.row.col): lane g*4+tg holds b_rg = halves (k=2tg+8rg, 2tg+1+8rg, n=g)
__global__ void mu_prep_kernel(const float* __restrict__ mu) {
    const int b = blockIdx.x;                 // 32 blocks
    const int ct = b >> 3, sub = b & 7;
    const int tid = threadIdx.x, w = tid >> 5, lane = tid & 31;
    uint32_t* dst = reinterpret_cast<uint32_t*>(g_mub[ct]);
    const float4* mp = reinterpret_cast<const float4*>(mu);
#pragma unroll
    for (int it = 0; it < 2; ++it) {
        int nl = sub * 16 + w + it * 8;           // local centroid 0..127
        float4 v = mp[(size_t)(ct * BN + nl) * 32 + lane];
        float p = warp_sum(v.x * v.x + v.y * v.y + v.z * v.z + v.w * v.w);
        if (lane == 0) g_m2[ct * BN + nl] = p;
        int nt = nl >> 3, gg = nl & 7;
        float e[4] = { v.x, v.y, v.z, v.w };
#pragma unroll
        for (int p2 = 0; p2 < 2; ++p2) {
            int c  = lane * 4 + 2 * p2;           // dim of pair start
            int ks = lane >> 2, cc = c & 15;
            int rg = cc >> 3, tg = (cc & 7) >> 1;
            dst[((nt * 8 + ks) * 32 + gg * 4 + tg) * 2 + rg] = h2bits(e[2 * p2], e[2 * p2 + 1]);
        }
    }
}

// ================= main kernel: fp16 mma.sync GEMM + min + fused reduce ====
__global__ void __launch_bounds__(NTHREADS, 2)
kmeans_mma_kernel(const float* __restrict__ z, float* __restrict__ out) {
    extern __shared__ uint32_t sm[];
    uint32_t* A_s  = sm;
    float* m2_s = reinterpret_cast<float*>(sm + M2_W);
    float* z2_s = reinterpret_cast<float*>(sm + Z2_W);
    float* sh   = reinterpret_cast<float*>(sm + SH_W);
    const uint32_t sb = smem_u32(sm);

    const int tid = threadIdx.x, w = tid >> 5, lane = tid & 31;
    const int warp_m = w >> 2, warp_n = w & 3;
    const int g = lane >> 2, tig = lane & 3;
    const int row0 = blockIdx.x * BM;
    const float4* zp = reinterpret_cast<const float4*>(z);

    // ---- prefetch B tile 0 first (overlaps with A staging) ----
    {
        const uint4* src = g_mub[0];
        for (int i = tid; i < BT_WORDS / 4; i += NTHREADS)
            cp_async16(sb + B_W(0) * 4 + i * 16, src + i);
        CP_COMMIT();
    }

    // ---- A staging: z -> fp16 fragment layout + exact fp32 z2 ----
    // A frag: lane g*4+tg holds a_j = halves (row g+8*(j&1), cols 2tg+8*(j>>1)+{0,1})
#pragma unroll
    for (int it = 0; it < 16; ++it) {
        int r = w + it * 8;
        float4 v = zp[(size_t)(row0 + r) * 32 + lane];
        float p = warp_sum(v.x * v.x + v.y * v.y + v.z * v.z + v.w * v.w);
        if (lane == 0) z2_s[r] = p;
        int mt = r >> 4, rr = r & 15, gg = rr & 7, jl = rr >> 3;
        float e[4] = { v.x, v.y, v.z, v.w };
#pragma unroll
        for (int p2 = 0; p2 < 2; ++p2) {
            int c  = lane * 4 + 2 * p2;
            int ks = lane >> 2, cc = c & 15;
            int hi = cc >> 3, tg = (cc & 7) >> 1;
            A_s[((mt * 8 + ks) * 33 + gg * 4 + tg) * 4 + jl + 2 * hi] =
                h2bits(e[2 * p2], e[2 * p2 + 1]);
        }
    }
    for (int i = tid; i < NCENT; i += NTHREADS) m2_s[i] = g_m2[i];

    float rowmin[8];
#pragma unroll
    for (int k = 0; k < 8; ++k) rowmin[k] = 3.402823466e38f;

    // ---- mainloop over 4 N-tiles, double-buffered B via cp.async ----
    for (int ct = 0; ct < NTILES; ++ct) {
        if (ct + 1 < NTILES) {
            const uint4* src = g_mub[ct + 1];
            uint32_t dst = sb + B_W((ct + 1) & 1) * 4;
            for (int i = tid; i < BT_WORDS / 4; i += NTHREADS)
                cp_async16(dst + i * 16, src + i);
            CP_COMMIT();
            CP_WAIT(1);               // tile ct resident
        } else {
            CP_WAIT(0);
        }
        __syncthreads();              // A staging (ct=0) + B visibility

        float acc[4][4][4];
#pragma unroll
        for (int mt = 0; mt < 4; ++mt)
#pragma unroll
            for (int nt = 0; nt < 4; ++nt)
#pragma unroll
                for (int q = 0; q < 4; ++q) acc[mt][nt][q] = 0.f;

        const uint32_t* Bbuf = sm + B_W(ct & 1);
#pragma unroll
        for (int ks = 0; ks < 8; ++ks) {
            uint32_t a[4][4], b[4][2];
#pragma unroll
            for (int mt = 0; mt < 4; ++mt)
                *reinterpret_cast<uint4*>(a[mt]) = *reinterpret_cast<const uint4*>(
                    &A_s[(((warp_m * 4 + mt) * 8 + ks) * 33 + lane) * 4]);
#pragma unroll
            for (int nt = 0; nt < 4; ++nt)
                *reinterpret_cast<uint2*>(b[nt]) = *reinterpret_cast<const uint2*>(
                    &Bbuf[(((warp_n * 4 + nt) * 8 + ks) * 32 + lane) * 2]);
#pragma unroll
            for (int mt = 0; mt < 4; ++mt)
#pragma unroll
                for (int nt = 0; nt < 4; ++nt)
                    mma_fp16(acc[mt][nt], a[mt], b[nt]);
        }

        // ---- epilogue: d2 = z2 + m2 - 2*dot, running min ----
        // D frag: c0=(g,2tig) c1=(g,2tig+1) c2=(g+8,2tig) c3=(g+8,2tig+1)
#pragma unroll
        for (int mt = 0; mt < 4; ++mt) {
            int rb = warp_m * 64 + mt * 16 + g;
            float z2a = z2_s[rb], z2b = z2_s[rb + 8];
#pragma unroll
            for (int nt = 0; nt < 4; ++nt) {
                int cb = ct * BN + warp_n * 32 + nt * 8 + 2 * tig;
                float m0 = m2_s[cb], m1 = m2_s[cb + 1];
                rowmin[mt * 2]     = fminf(rowmin[mt * 2],
                                           fmaf(-2.f, acc[mt][nt][0], z2a + m0));
                rowmin[mt * 2]     = fminf(rowmin[mt * 2],
                                           fmaf(-2.f, acc[mt][nt][1], z2a + m1));
                rowmin[mt * 2 + 1] = fminf(rowmin[mt * 2 + 1],
                                           fmaf(-2.f, acc[mt][nt][2], z2b + m0));
                rowmin[mt * 2 + 1] = fminf(rowmin[mt * 2 + 1],
                                           fmaf(-2.f, acc[mt][nt][3], z2b + m1));
            }
        }
        __syncthreads();              // buf[ct&1] reads done before reuse
    }

    // ---- min across 4 tig lanes, sqrt, sum within block ----
#pragma unroll
    for (int k = 0; k < 8; ++k) {
        float v = rowmin[k];
        v = fminf(v, __shfl_xor_sync(0xffffffffu, v, 1));
        v = fminf(v, __shfl_xor_sync(0xffffffffu, v, 2));
        rowmin[k] = v;
    }
    // reuse A_s region for the 128x4 min matrix
    float* red = reinterpret_cast<float*>(A_s);
    if (tig == 0) {
#pragma unroll
        for (int mt = 0; mt < 4; ++mt) {
            red[(warp_m * 64 + mt * 16 + g) * 4 + warp_n]     = rowmin[mt * 2];
            red[(warp_m * 64 + mt * 16 + 8 + g) * 4 + warp_n] = rowmin[mt * 2 + 1];
        }
    }
    __syncthreads();

    float dist = 0.f;
    if (tid < BM) {
        float m = fminf(fminf(red[tid * 4], red[tid * 4 + 1]),
                        fminf(red[tid * 4 + 2], red[tid * 4 + 3]));
        dist = sqrtf(fmaxf(m, 0.f));
    }
#pragma unroll
    for (int o = 16; o; o >>= 1) dist += __shfl_down_sync(0xffffffffu, dist, o);
    if (lane == 0) sh[w] = dist;
    __syncthreads();
    if (tid == 0) {
        float s = 0.f;
#pragma unroll
        for (int i = 0; i < 8; i++) s += sh[i];
        g_partials[blockIdx.x] = s;
    }
    __threadfence();

    // ---- fused deterministic final reduction: last block sums all partials ----
    __shared__ unsigned lastflag;
    if (tid == 0) lastflag = atomicInc(&g_done, NBLK - 1);  // wraps back to 0
    __syncthreads();
    if (lastflag == NBLK - 1) {
        __threadfence();
        float v = g_partials[tid] + g_partials[tid + NTHREADS];
#pragma unroll
        for (int o = 16; o; o >>= 1) v += __shfl_down_sync(0xffffffffu, v, o);
        if (lane == 0) sh[w] = v;
        __syncthreads();
        if (tid == 0) {
            float s = 0.f;
#pragma unroll
            for (int i = 0; i < 8; i++) s += sh[i];
            out[0] = s / (float)NROWS;
        }
    }
}

// ---------------------------------------------------------------------------
extern "C" void kernel_launch(void* const* d_in, const int* in_sizes, int n_in,
                              void* d_out, int out_size) {
    const float* z  = (const float*)d_in[0];   // (65536,1,128) contiguous
    const float* mu = (const float*)d_in[1];   // (512,128)
    float* out = (float*)d_out;

    cudaFuncSetAttribute(kmeans_mma_kernel,
                         cudaFuncAttributeMaxDynamicSharedMemorySize, SMEM_BYTES);

    mu_prep_kernel<<<NTILES * 8, NTHREADS>>>(mu);
    kmeans_mma_kernel<<<NBLK, NTHREADS, SMEM_BYTES>>>(z, out);
}